// round 4
// baseline (speedup 1.0000x reference)
#include <cuda_runtime.h>

// Problem constants (SUBDIVISIONS=7, BATCH=16)
#define BATCH 16
#define YDIM  640
#define XDIM  256
#define BH    128            // YDIM/5
#define YX    (YDIM*XDIM)    // 163840
#define NV    (YX + 2)       // 163842 vertices
#define BPT   4              // batches per thread in the fused loss kernel

// Scratch (static __device__ — no allocation allowed)
__device__ float4 g_v4[BATCH * NV];   // padded xyz_ per batch (~42 MB)
__device__ int    g_cnt[NV];          // per-vertex ring fill counters
__device__ int2   g_ring[NV * 6];     // per-vertex opposite-edge pairs (a,b)
__device__ double g_acc;              // fused loss accumulator
__device__ unsigned int g_done;       // ticket counter for fused finalization

// ---------------------------------------------------------------------------
// K1: build v = [grid verts ; top pole ; bottom pole] as float4 (w unused).
// Also zeroes g_cnt / g_acc / g_done (b==0 slice) — replaces k_zero.
// inputs layout: (B, 3, Y, X) row-major
// ---------------------------------------------------------------------------
__global__ void k_build_v(const float* __restrict__ inp) {
    int vtx = blockIdx.x * blockDim.x + threadIdx.x;
    int b   = blockIdx.y;
    if (vtx > YX + 1) return;
    if (b == 0) {
        g_cnt[vtx] = 0;
        if (vtx == 0) { g_acc = 0.0; g_done = 0u; }
    }
    const float* base = inp + (size_t)b * 3 * YX;
    float4 o;
    o.w = 0.0f;
    if (vtx < YX) {
        o.x = base[vtx];
        o.y = base[YX + vtx];
        o.z = base[2 * YX + vtx];
    } else if (vtx == YX) {
        float s[3];
        #pragma unroll
        for (int c = 0; c < 3; c++) {
            s[c] = 0.0f;
            #pragma unroll
            for (int i = 0; i < 5; i++) s[c] += base[c * YX + (i * BH) * XDIM];
            s[c] *= 0.2f;
        }
        o.x = s[0]; o.y = s[1]; o.z = s[2];
    } else {
        float s[3];
        #pragma unroll
        for (int c = 0; c < 3; c++) {
            s[c] = 0.0f;
            #pragma unroll
            for (int i = 1; i <= 5; i++)
                s[c] += base[c * YX + (i * BH - 1) * XDIM + (XDIM - 1)];
            s[c] *= 0.2f;
        }
        o.x = s[0]; o.y = s[1]; o.z = s[2];
    }
    g_v4[(size_t)b * NV + vtx] = o;
}

// ---------------------------------------------------------------------------
// K2: collect per-vertex opposite-edge pairs from faces (batch-independent).
// Face (f0,f1,f2): pair (f1,f2)->f0, (f2,f0)->f1, (f0,f1)->f2.
// Identity: summing full face normals around a closed ring telescopes to
// vn[v] = sum_i a_i x b_i over opposite-edge pairs.
// ---------------------------------------------------------------------------
__global__ void k_ring(const int* __restrict__ faces, int F) {
    int f = blockIdx.x * blockDim.x + threadIdx.x;
    if (f >= F) return;
    int a = faces[3 * f], b = faces[3 * f + 1], c = faces[3 * f + 2];
    int s;
    s = atomicAdd(&g_cnt[a], 1); g_ring[a * 6 + s] = make_int2(b, c);
    s = atomicAdd(&g_cnt[b], 1); g_ring[b * 6 + s] = make_int2(c, a);
    s = atomicAdd(&g_cnt[c], 1); g_ring[c * 6 + s] = make_int2(a, b);
}

// ---------------------------------------------------------------------------
// K3: fused loss. One thread per vertex, BPT batches per thread.
// Chains the opposite-edge pairs into cyclic ring order in registers
// (succ(b)=c), so vn = sum_j n_j x n_{j+1 mod 6}; for deg-5 the 6th slot
// duplicates n_0 making its wrap cross term vanish. degree == ring count.
// Last block (ticket) writes the final scalar — no separate k_final.
// ---------------------------------------------------------------------------
__global__ void __launch_bounds__(128, 8)
k_loss(const float* __restrict__ target, float* __restrict__ out,
       unsigned int nblocks) {
    int vtx = blockIdx.x * blockDim.x + threadIdx.x;
    float local = 0.0f;
    if (vtx < NV) {
        int cnt = g_cnt[vtx];            // 5 or 6 == degree
        int2 pr[6];
        #pragma unroll
        for (int i = 0; i < 6; i++)
            pr[i] = (i < cnt) ? g_ring[vtx * 6 + i] : make_int2(-1, -1);
        int n[6];
        n[0] = pr[0].x;
        int cur = pr[0].y;
        #pragma unroll
        for (int k = 1; k < 6; k++) {
            n[k] = cur;
            int nxt = cur;
            #pragma unroll
            for (int i = 0; i < 6; i++)
                if (pr[i].x == cur) nxt = pr[i].y;
            cur = nxt;
        }
        if (cnt == 5) n[5] = n[0];       // duplicated: wrap cross term = 0

        float invd = 1.0f / (float)cnt;
        const float inv3 = 1.0f / 3.0f;

        #pragma unroll
        for (int bb = 0; bb < BPT; bb++) {
            int b = blockIdx.y * BPT + bb;
            const float4* vb = g_v4 + (size_t)b * NV;

            float4 p[6];
            #pragma unroll
            for (int i = 0; i < 6; i++) p[i] = __ldg(vb + n[i]);
            float4 pv = __ldg(vb + vtx);

            // ring-ordered cross sum: vn = sum_j p_j x p_{(j+1)%6}
            float nx = 0.f, ny = 0.f, nz = 0.f;
            #pragma unroll
            for (int j = 0; j < 6; j++) {
                const float4 a = p[j];
                const float4 c = p[(j + 1) % 6];
                nx += a.y * c.z - a.z * c.y;
                ny += a.z * c.x - a.x * c.z;
                nz += a.x * c.y - a.y * c.x;
            }
            // neighbor sum (subtract the duplicated n0 if deg==5)
            float sx = 0.f, sy = 0.f, sz = 0.f;
            #pragma unroll
            for (int j = 0; j < 6; j++) { sx += p[j].x; sy += p[j].y; sz += p[j].z; }
            if (cnt == 5) { sx -= p[0].x; sy -= p[0].y; sz -= p[0].z; }

            const float* t = target + (size_t)b * 9 * NV + vtx;
            // position loss
            float dx = pv.x - t[0];
            float dy = pv.y - t[(size_t)NV];
            float dz = pv.z - t[2 * (size_t)NV];
            float lpos = dx * dx + dy * dy + dz * dz;
            // normal cosine loss
            float nn  = sqrtf(nx * nx + ny * ny + nz * nz);
            float inv = 1.0f / fmaxf(nn, 1e-12f);
            float ux = nx * inv, uy = ny * inv, uz = nz * inv;
            float un = sqrtf(ux * ux + uy * uy + uz * uz);
            float tx = t[3 * (size_t)NV], ty = t[4 * (size_t)NV], tz = t[5 * (size_t)NV];
            float tn = sqrtf(tx * tx + ty * ty + tz * tz);
            float cosv = (ux * tx + uy * ty + uz * tz) / fmaxf(un * tn, 1e-8f);
            // Laplacian loss
            float dlx = (pv.x - sx * invd) - t[6 * (size_t)NV];
            float dly = (pv.y - sy * invd) - t[7 * (size_t)NV];
            float dlz = (pv.z - sz * invd) - t[8 * (size_t)NV];
            float llap = dlx * dlx + dly * dly + dlz * dlz;

            local += (lpos + llap) * inv3 + (1.0f - cosv);
        }
    }

    // warp shuffle reduce, then cross-warp smem reduce, one atomic per block
    #pragma unroll
    for (int off = 16; off > 0; off >>= 1)
        local += __shfl_xor_sync(0xFFFFFFFFu, local, off);
    __shared__ float shw[4];
    int wid = threadIdx.x >> 5;
    if ((threadIdx.x & 31) == 0) shw[wid] = local;
    __syncthreads();
    if (threadIdx.x == 0) {
        float s = shw[0] + shw[1] + shw[2] + shw[3];
        atomicAdd(&g_acc, (double)s);
        __threadfence();
        unsigned int ticket = atomicAdd(&g_done, 1u);
        if (ticket == nblocks - 1u) {
            // all other blocks' g_acc contributions are visible (atomic order)
            out[0] = (float)(g_acc / ((double)BATCH * (double)NV));
        }
    }
}

extern "C" void kernel_launch(void* const* d_in, const int* in_sizes, int n_in,
                              void* d_out, int out_size) {
    const float* inputs = (const float*)d_in[0];
    const float* target = (const float*)d_in[1];
    const int*   faces  = (const int*)  d_in[2];
    int F = in_sizes[2] / 3;

    dim3 blk256(256);
    k_build_v<<<dim3((YX + 2 + 255) / 256, BATCH), blk256>>>(inputs);
    k_ring   <<<(F + 255) / 256, blk256>>>(faces, F);
    dim3 lgrid((NV + 127) / 128, BATCH / BPT);
    unsigned int nblocks = lgrid.x * lgrid.y;
    k_loss   <<<lgrid, 128>>>(target, (float*)d_out, nblocks);
}